// round 6
// baseline (speedup 1.0000x reference)
#include <cuda_runtime.h>
#include <cuda_bf16.h>
#include <cstdint>

#define DINL __device__ __forceinline__

// ======================= helpers =======================
DINL uint32_t smem_u32(const void* p) {
    uint32_t a;
    asm("{ .reg .u64 t; cvta.to.shared.u64 t, %1; cvt.u32.u64 %0, t; }" : "=r"(a) : "l"(p));
    return a;
}
DINL void ldsm_x4(uint32_t r[4], uint32_t addr) {
    asm volatile("ldmatrix.sync.aligned.m8n8.x4.shared.b16 {%0,%1,%2,%3}, [%4];"
        : "=r"(r[0]), "=r"(r[1]), "=r"(r[2]), "=r"(r[3]) : "r"(addr));
}
DINL void ldsm_x2(uint32_t r[2], uint32_t addr) {
    asm volatile("ldmatrix.sync.aligned.m8n8.x2.shared.b16 {%0,%1}, [%2];"
        : "=r"(r[0]), "=r"(r[1]) : "r"(addr));
}
DINL void mma_bf16(float c[4], const uint32_t a[4], const uint32_t b[2]) {
    asm volatile("mma.sync.aligned.m16n8k16.row.col.f32.bf16.bf16.f32 "
        "{%0,%1,%2,%3}, {%4,%5,%6,%7}, {%8,%9}, {%0,%1,%2,%3};"
        : "+f"(c[0]), "+f"(c[1]), "+f"(c[2]), "+f"(c[3])
        : "r"(a[0]), "r"(a[1]), "r"(a[2]), "r"(a[3]), "r"(b[0]), "r"(b[1]));
}
#define STS32(a, v) asm volatile("st.shared.b32 [%0], %1;" :: "r"(a), "r"(v) : "memory")
#define STS64(a, v) asm volatile("st.shared.b64 [%0], %1;" :: "r"(a), "l"(v) : "memory")

DINL uint32_t pack2(float a, float b) {
    return ((uint32_t)__bfloat16_as_ushort(__float2bfloat16(b)) << 16)
         |  (uint32_t)__bfloat16_as_ushort(__float2bfloat16(a));
}
DINL uint64_t pack4(float a, float b, float c, float d) {
    return ((uint64_t)pack2(c, d) << 32) | (uint64_t)pack2(a, b);
}
DINL float rlo(float f) { return f - __bfloat162float(__float2bfloat16(f)); }

// ======================= SMEM layout =======================
// A0 hi[0,8K) lo[8K,16K) | A1 hi[16K,24K) lo[24K,32K)
// H0 hi[32K,40K) lo[40K,48K) | H1 hi[48K,56K) lo[56K,64K)
// W1lo [64K,96K) | W2lo [96K,128K)
static constexpr int OFF_H   = 32768;
static constexpr int OFF_W1L = 65536;
static constexpr int OFF_W2L = 98304;
static constexpr int SMEM_TOTAL = 131072;

// ======================= device globals =======================
__device__ __align__(16) uint32_t g_whi[2][8192];        // [n][kword] bf16x2: W1h, W2h
__device__ __align__(16) unsigned char g_wlo[2][32768];  // swizzled [n][k]: W1l, W2l
__device__ int g_idx64;
static constexpr int IDX_CAP = 1 << 20;
__device__ int g_idxp[IDX_CAP];

// ======================= prologues =======================
__global__ void prep_w(const float* __restrict__ W1, const float* __restrict__ W2,
                       const void* __restrict__ nbr_raw) {
    int n = blockIdx.x, k = threadIdx.x;
    float w1e = W1[k * 128 + n] + W1[(k + 128) * 128 + n];  // fold concat
    float w2v = W2[k * 128 + n];
    __nv_bfloat16 h1 = __float2bfloat16(w1e);
    __nv_bfloat16 l1 = __float2bfloat16(w1e - __bfloat162float(h1));
    __nv_bfloat16 h2 = __float2bfloat16(w2v);
    __nv_bfloat16 l2 = __float2bfloat16(w2v - __bfloat162float(h2));
    ((__nv_bfloat16*)g_whi[0])[n * 128 + k] = h1;
    ((__nv_bfloat16*)g_whi[1])[n * 128 + k] = h2;
    uint32_t ta = (uint32_t)(n * 256 + (((k >> 3) ^ (n & 7)) << 4) + ((k & 7) << 1));
    *(__nv_bfloat16*)(g_wlo[0] + ta) = l1;
    *(__nv_bfloat16*)(g_wlo[1] + ta) = l2;
    if (blockIdx.x == 0 && threadIdx.x == 0) {
        const unsigned* w = (const unsigned*)nbr_raw;
        int is64 = 1;
        for (int i = 0; i < 64; i++)
            if (w[2 * i + 1] != 0u) { is64 = 0; break; }
        g_idx64 = is64;
    }
}

__global__ void prep_idx(const void* __restrict__ nbr_raw, int E) {
    int i = blockIdx.x * 256 + threadIdx.x;
    if (i >= E || i >= IDX_CAP) return;
    long long v = g_idx64 ? ((const long long*)nbr_raw)[i]
                          : (long long)((const int*)nbr_raw)[i];
    g_idxp[i] = ((int)v) << 7;
}

// ======================= main kernel =======================
__global__ void __launch_bounds__(512, 1)
gs_kernel(const float* __restrict__ x,
          const float* __restrict__ b1, const float* __restrict__ b2,
          float* __restrict__ out, int E) {
    extern __shared__ unsigned char sm[];
    const uint32_t sb = smem_u32(sm);
    const int tid = threadIdx.x, wid = tid >> 5, lane = tid & 31;
    const int mg = wid >> 3, ng = wid & 7;          // 2 M-groups x 8 N-groups

    // ---- W-lo tiles -> SMEM ----
    {
        const uint4* s = (const uint4*)g_wlo;
        uint4* d = (uint4*)(sm + OFF_W1L);
#pragma unroll
        for (int i = tid; i < 65536 / 16; i += 512) d[i] = s[i];
    }

    // ---- persistent B-hi fragments ----
    uint32_t B1h[2][8][2], B2h[2][8][2];
    {
        const int lc = lane & 3;
#pragma unroll
        for (int ch = 0; ch < 2; ch++) {
            const int nb = (ng * 16 + ch * 8 + (lane >> 2)) * 64;
#pragma unroll
            for (int ks = 0; ks < 8; ks++)
#pragma unroll
                for (int j = 0; j < 2; j++) {
                    const int wi = nb + ks * 8 + j * 4 + lc;
                    B1h[ch][ks][j] = g_whi[0][wi];
                    B2h[ch][ks][j] = g_whi[1][wi];
                }
        }
    }
    float b1r[2][2], b2r[2][2];
#pragma unroll
    for (int ch = 0; ch < 2; ch++) {
        const int n0 = ng * 16 + ch * 8 + (lane & 3) * 2;
        b1r[ch][0] = b1[n0]; b1r[ch][1] = b1[n0 + 1];
        b2r[ch][0] = b2[n0]; b2r[ch][1] = b2[n0 + 1];
    }

    // ldmatrix lane addressing
    const int li = lane & 7, lg = lane >> 3;
    const int arow = ((lg & 1) << 3) + li;
    const int akh = lg >> 1;
    const uint32_t aoff = (uint32_t)(mg * 4096 + arow * 256);
    const int arx = arow & 7;
    const int bg = lg & 1;
    const uint32_t bl_row0 = (uint32_t)((ng * 16 + li) * 256);
    const uint32_t bl_row1 = (uint32_t)((ng * 16 + 8 + li) * 256);
    const int blx0 = (ng * 16 + li) & 7, blx1 = (ng * 16 + 8 + li) & 7;

    const uint32_t W1L = sb + OFF_W1L, W2L = sb + OFF_W2L;

    const int ntiles = (E + 31) >> 5;
    const int stride = gridDim.x;
    if (blockIdx.x >= ntiles) return;

    // gather addressing
    const uint32_t gwithin = (uint32_t)((lane & 1) << 3);
    const int gc = lane >> 1;
    const int gr_base = wid * 2;
    const int r0g = gr_base, r1g = r0g + 1;
    const uint32_t ga0 = (uint32_t)(r0g * 256) + (uint32_t)((gc ^ (r0g & 7)) << 4) + gwithin;
    const uint32_t ga1 = (uint32_t)(r1g * 256) + (uint32_t)((gc ^ (r1g & 7)) << 4) + gwithin;

    // h epilogue addressing
    const int hr0 = mg * 16 + (lane >> 2), hr1 = hr0 + 8;
    uint32_t hadr[2][2];
#pragma unroll
    for (int ch = 0; ch < 2; ch++) {
        const int col = ng * 16 + ch * 8 + (lane & 3) * 2;
        const uint32_t u = (uint32_t)(col >> 3), w0 = (uint32_t)((col & 7) << 1);
        hadr[ch][0] = (uint32_t)(hr0 * 256) + (((u ^ (uint32_t)(hr0 & 7))) << 4) + w0;
        hadr[ch][1] = (uint32_t)(hr1 * 256) + (((u ^ (uint32_t)(hr1 & 7))) << 4) + w0;
    }

#define GATHER_LDG(T, V0, V1) do {                                        \
        const int gr = ((T) << 5) + gr_base;                              \
        const int o0 = (gr < E) ? g_idxp[gr] : 0;                         \
        const int o1 = (gr + 1 < E) ? g_idxp[gr + 1] : 0;                 \
        V0 = *(const float4*)(x + o0 + (lane << 2));                      \
        V1 = *(const float4*)(x + o1 + (lane << 2));                      \
    } while (0)

#define GATHER_STS(BASE, V0, V1) do {                                     \
        STS64((BASE) + ga0, pack4(V0.x, V0.y, V0.z, V0.w));               \
        STS64((BASE) + 8192u + ga0, pack4(rlo(V0.x), rlo(V0.y), rlo(V0.z), rlo(V0.w))); \
        STS64((BASE) + ga1, pack4(V1.x, V1.y, V1.z, V1.w));               \
        STS64((BASE) + 8192u + ga1, pack4(rlo(V1.x), rlo(V1.y), rlo(V1.z), rlo(V1.w))); \
    } while (0)

#define H_EPILOGUE(ACC, HBASE) do {                                       \
        _Pragma("unroll")                                                 \
        for (int ch = 0; ch < 2; ch++) {                                  \
            const float f0 = fmaxf(ACC[ch][0] + b1r[ch][0], 0.f);         \
            const float f1 = fmaxf(ACC[ch][1] + b1r[ch][1], 0.f);         \
            const float f2 = fmaxf(ACC[ch][2] + b1r[ch][0], 0.f);         \
            const float f3 = fmaxf(ACC[ch][3] + b1r[ch][1], 0.f);         \
            STS32((HBASE) + hadr[ch][0], pack2(f0, f1));                  \
            STS32((HBASE) + 8192u + hadr[ch][0], pack2(rlo(f0), rlo(f1)));\
            STS32((HBASE) + hadr[ch][1], pack2(f2, f3));                  \
            STS32((HBASE) + 8192u + hadr[ch][1], pack2(rlo(f2), rlo(f3)));\
        }                                                                  \
    } while (0)

    // ================= preamble =================
    // gather(tile0) -> A[0]
    {
        float4 v0, v1;
        GATHER_LDG(blockIdx.x, v0, v1);
        GATHER_STS(sb, v0, v1);
    }
    __syncthreads();

    // GEMM1(tile0) -> H[0]; gather(tile1) -> A[1]
    {
        const int t1 = blockIdx.x + stride;
        float4 v0, v1;
        if (t1 < ntiles) GATHER_LDG(t1, v0, v1);

        float acc[2][4] = {{0,0,0,0},{0,0,0,0}};
#pragma unroll
        for (int ks = 0; ks < 8; ks++) {
            const uint32_t c = (uint32_t)((((ks << 1) + akh) ^ arx) << 4);
            uint32_t Ah[4], Al[4], Bl0[2], Bl1[2];
            ldsm_x4(Ah, sb + aoff + c);
            ldsm_x4(Al, sb + 8192u + aoff + c);
            ldsm_x2(Bl0, W1L + bl_row0 + (uint32_t)((((ks << 1) + bg) ^ blx0) << 4));
            ldsm_x2(Bl1, W1L + bl_row1 + (uint32_t)((((ks << 1) + bg) ^ blx1) << 4));
            mma_bf16(acc[0], Ah, B1h[0][ks]);
            mma_bf16(acc[1], Ah, B1h[1][ks]);
            mma_bf16(acc[0], Ah, Bl0);
            mma_bf16(acc[1], Ah, Bl1);
            mma_bf16(acc[0], Al, B1h[0][ks]);
            mma_bf16(acc[1], Al, B1h[1][ks]);
        }
        H_EPILOGUE(acc, sb + OFF_H);
        if (t1 < ntiles) GATHER_STS(sb + 16384u, v0, v1);
    }
    __syncthreads();

    // ================= pipelined main loop =================
    for (int p = 0;; p++) {
        const int t = blockIdx.x + p * stride;
        if (t >= ntiles) break;
        const int t1 = t + stride;
        const int t2 = t + 2 * stride;
        const bool hasG1 = (t1 < ntiles);
        const uint32_t AR = sb + (uint32_t)((p + 1) & 1) * 16384u;   // A for GEMM1(t1)
        const uint32_t AW = sb + (uint32_t)(p & 1) * 16384u;         // gather target
        const uint32_t HR = sb + OFF_H + (uint32_t)(p & 1) * 16384u; // h(t)
        const uint32_t HW = sb + OFF_H + (uint32_t)((p + 1) & 1) * 16384u;

        float4 v0, v1;
        if (t2 < ntiles) GATHER_LDG(t2, v0, v1);

        float acc1[2][4] = {{0,0,0,0},{0,0,0,0}};
        float acc2[2][4] = {{0,0,0,0},{0,0,0,0}};
#pragma unroll
        for (int ks = 0; ks < 8; ks++) {
            const uint32_t c = (uint32_t)((((ks << 1) + akh) ^ arx) << 4);
            const uint32_t cb0 = (uint32_t)((((ks << 1) + bg) ^ blx0) << 4);
            const uint32_t cb1 = (uint32_t)((((ks << 1) + bg) ^ blx1) << 4);
            // GEMM2 fragment loads
            uint32_t A2h[4], A2l[4], Bl20[2], Bl21[2];
            ldsm_x4(A2h, HR + aoff + c);
            ldsm_x4(A2l, HR + 8192u + aoff + c);
            ldsm_x2(Bl20, W2L + bl_row0 + cb0);
            ldsm_x2(Bl21, W2L + bl_row1 + cb1);
            // GEMM2 MMAs
            mma_bf16(acc2[0], A2h, B2h[0][ks]);
            mma_bf16(acc2[1], A2h, B2h[1][ks]);
            mma_bf16(acc2[0], A2h, Bl20);
            mma_bf16(acc2[1], A2h, Bl21);
            mma_bf16(acc2[0], A2l, B2h[0][ks]);
            mma_bf16(acc2[1], A2l, B2h[1][ks]);
            if (hasG1) {
                uint32_t A1h[4], A1l[4], Bl10[2], Bl11[2];
                ldsm_x4(A1h, AR + aoff + c);
                ldsm_x4(A1l, AR + 8192u + aoff + c);
                ldsm_x2(Bl10, W1L + bl_row0 + cb0);
                ldsm_x2(Bl11, W1L + bl_row1 + cb1);
                mma_bf16(acc1[0], A1h, B1h[0][ks]);
                mma_bf16(acc1[1], A1h, B1h[1][ks]);
                mma_bf16(acc1[0], A1h, Bl10);
                mma_bf16(acc1[1], A1h, Bl11);
                mma_bf16(acc1[0], A1l, B1h[0][ks]);
                mma_bf16(acc1[1], A1l, B1h[1][ks]);
            }
        }

        // gather store into A[p&1]
        if (t2 < ntiles) GATHER_STS(AW, v0, v1);

        // GEMM1 epilogue -> H[(p+1)&1]
        if (hasG1) H_EPILOGUE(acc1, HW);

        // GEMM2 epilogue -> global
        {
            const int rg0 = (t << 5) + hr0, rg1 = (t << 5) + hr1;
#pragma unroll
            for (int ch = 0; ch < 2; ch++) {
                const int col = ng * 16 + ch * 8 + (lane & 3) * 2;
                if (rg0 < E)
                    *(float2*)(out + (size_t)rg0 * 128 + col) =
                        make_float2(acc2[ch][0] + b2r[ch][0], acc2[ch][1] + b2r[ch][1]);
                if (rg1 < E)
                    *(float2*)(out + (size_t)rg1 * 128 + col) =
                        make_float2(acc2[ch][2] + b2r[ch][0], acc2[ch][3] + b2r[ch][1]);
            }
        }
        __syncthreads();
    }
#undef GATHER_LDG
#undef GATHER_STS
#undef H_EPILOGUE
}

// ======================= launch =======================
extern "C" void kernel_launch(void* const* d_in, const int* in_sizes, int n_in,
                              void* d_out, int out_size) {
    const float* x  = (const float*)d_in[0];
    const void*  nb = d_in[1];
    const float* W1 = (const float*)d_in[2];
    const float* b1 = (const float*)d_in[3];
    const float* W2 = (const float*)d_in[4];
    const float* b2 = (const float*)d_in[5];
    float* out = (float*)d_out;
    const int E = in_sizes[1];

    prep_w<<<128, 128>>>(W1, W2, nb);
    prep_idx<<<(E + 255) / 256, 256>>>(nb, E);

    int dev = 0;
    cudaGetDevice(&dev);
    int sms = 148;
    cudaDeviceGetAttribute(&sms, cudaDevAttrMultiProcessorCount, dev);
    const int ntiles = (E + 31) >> 5;
    int grid = sms;
    if (grid > ntiles) grid = ntiles;

    cudaFuncSetAttribute(gs_kernel, cudaFuncAttributeMaxDynamicSharedMemorySize, SMEM_TOTAL);
    gs_kernel<<<grid, 512, SMEM_TOTAL>>>(x, b1, b2, out, E);
}

// round 7
// speedup vs baseline: 1.2905x; 1.2905x over previous
#include <cuda_runtime.h>
#include <cuda_bf16.h>
#include <cstdint>

#define DINL __device__ __forceinline__

// ======================= helpers =======================
DINL uint32_t smem_u32(const void* p) {
    uint32_t a;
    asm("{ .reg .u64 t; cvta.to.shared.u64 t, %1; cvt.u32.u64 %0, t; }" : "=r"(a) : "l"(p));
    return a;
}
DINL void ldsm_x4(uint32_t r[4], uint32_t addr) {
    asm volatile("ldmatrix.sync.aligned.m8n8.x4.shared.b16 {%0,%1,%2,%3}, [%4];"
        : "=r"(r[0]), "=r"(r[1]), "=r"(r[2]), "=r"(r[3]) : "r"(addr));
}
DINL void ldsm_x2(uint32_t r[2], uint32_t addr) {
    asm volatile("ldmatrix.sync.aligned.m8n8.x2.shared.b16 {%0,%1}, [%2];"
        : "=r"(r[0]), "=r"(r[1]) : "r"(addr));
}
DINL void mma_bf16(float c[4], const uint32_t a[4], const uint32_t b[2]) {
    asm volatile("mma.sync.aligned.m16n8k16.row.col.f32.bf16.bf16.f32 "
        "{%0,%1,%2,%3}, {%4,%5,%6,%7}, {%8,%9}, {%0,%1,%2,%3};"
        : "+f"(c[0]), "+f"(c[1]), "+f"(c[2]), "+f"(c[3])
        : "r"(a[0]), "r"(a[1]), "r"(a[2]), "r"(a[3]), "r"(b[0]), "r"(b[1]));
}
#define STS32(a, v) asm volatile("st.shared.b32 [%0], %1;" :: "r"(a), "r"(v) : "memory")
#define STS64(a, v) asm volatile("st.shared.b64 [%0], %1;" :: "r"(a), "l"(v) : "memory")
#define BAR_GRP(id) asm volatile("bar.sync %0, 256;" :: "r"(id) : "memory")

DINL uint32_t pack2(float a, float b) {
    return ((uint32_t)__bfloat16_as_ushort(__float2bfloat16(b)) << 16)
         |  (uint32_t)__bfloat16_as_ushort(__float2bfloat16(a));
}
DINL uint64_t pack4(float a, float b, float c, float d) {
    return ((uint64_t)pack2(c, d) << 32) | (uint64_t)pack2(a, b);
}
DINL float rlo(float f) { return f - __bfloat162float(__float2bfloat16(f)); }

// ======================= SMEM layout =======================
// W1lo [0,32K) | W2lo [32K,64K)
// group g at 64K + g*48K: A0 hi/lo 16K | A1 hi/lo 16K | H hi/lo 16K
// biases at 160K: b1 512B, b2 512B
static constexpr int OFF_GRP  = 65536;
static constexpr int GRP_SIZE = 49152;
static constexpr int OFF_B1   = 163840;
static constexpr int OFF_B2   = 164352;
static constexpr int SMEM_TOTAL = 164864;

// ======================= device globals =======================
__device__ __align__(16) uint32_t g_whi[2][8192];        // [n][kword] bf16x2: W1h, W2h
__device__ __align__(16) unsigned char g_wlo[2][32768];  // swizzled [n][k]: W1l, W2l
static constexpr int IDX_CAP = 1 << 20;
__device__ int g_idxp[IDX_CAP];

// ======================= merged prologue (1 launch) =======================
__global__ void prep_all(const float* __restrict__ W1, const float* __restrict__ W2,
                         const void* __restrict__ nbr_raw, int E) {
    __shared__ int s_is64;
    if (threadIdx.x == 0) {
        const unsigned* w = (const unsigned*)nbr_raw;
        int is64 = 1;
        for (int i = 0; i < 64; i++)
            if (w[2 * i + 1] != 0u) { is64 = 0; break; }
        s_is64 = is64;
    }
    __syncthreads();
    const int i = blockIdx.x * 256 + threadIdx.x;
    if (i < E && i < IDX_CAP) {
        long long v = s_is64 ? ((const long long*)nbr_raw)[i]
                             : (long long)((const int*)nbr_raw)[i];
        g_idxp[i] = ((int)v) << 7;
    }
    if (blockIdx.x < 128 && threadIdx.x < 128) {
        const int n = blockIdx.x, k = threadIdx.x;
        float w1e = W1[k * 128 + n] + W1[(k + 128) * 128 + n];  // fold concat
        float w2v = W2[k * 128 + n];
        __nv_bfloat16 h1 = __float2bfloat16(w1e);
        __nv_bfloat16 l1 = __float2bfloat16(w1e - __bfloat162float(h1));
        __nv_bfloat16 h2 = __float2bfloat16(w2v);
        __nv_bfloat16 l2 = __float2bfloat16(w2v - __bfloat162float(h2));
        ((__nv_bfloat16*)g_whi[0])[n * 128 + k] = h1;
        ((__nv_bfloat16*)g_whi[1])[n * 128 + k] = h2;
        uint32_t ta = (uint32_t)(n * 256 + (((k >> 3) ^ (n & 7)) << 4) + ((k & 7) << 1));
        *(__nv_bfloat16*)(g_wlo[0] + ta) = l1;
        *(__nv_bfloat16*)(g_wlo[1] + ta) = l2;
    }
}

// ======================= main kernel =======================
__global__ void __launch_bounds__(512, 1)
gs_kernel(const float* __restrict__ x,
          const float* __restrict__ b1, const float* __restrict__ b2,
          float* __restrict__ out, int E) {
    extern __shared__ unsigned char sm[];
    const uint32_t sb = smem_u32(sm);
    const int tid = threadIdx.x, wid = tid >> 5, lane = tid & 31;
    const int grp = wid >> 3, ng = wid & 7;   // 2 groups x 8 N-warps

    // ---- W-lo tiles + biases -> SMEM ----
    {
        const uint4* s = (const uint4*)g_wlo;
        uint4* d = (uint4*)sm;
#pragma unroll
        for (int i = tid; i < 65536 / 16; i += 512) d[i] = s[i];
    }
    if (tid < 128) {
        ((float*)(sm + OFF_B1))[tid] = b1[tid];
        ((float*)(sm + OFF_B2))[tid] = b2[tid];
    }
    __syncthreads();

    // ---- persistent B-hi fragments (16 cols, both GEMMs) ----
    uint32_t B1h[2][8][2], B2h[2][8][2];
    {
        const int lc = lane & 3;
#pragma unroll
        for (int ch = 0; ch < 2; ch++) {
            const int nb = (ng * 16 + ch * 8 + (lane >> 2)) * 64;
#pragma unroll
            for (int ks = 0; ks < 8; ks++)
#pragma unroll
                for (int j = 0; j < 2; j++) {
                    const int wi = nb + ks * 8 + j * 4 + lc;
                    B1h[ch][ks][j] = g_whi[0][wi];
                    B2h[ch][ks][j] = g_whi[1][wi];
                }
        }
    }

    // ldmatrix lane addressing
    const int li = lane & 7, lg = lane >> 3;
    const int arow = ((lg & 1) << 3) + li;
    const int akh = lg >> 1;
    const uint32_t arowoff = (uint32_t)(arow * 256);
    const int arx = arow & 7;
    const int bg = lg & 1;
    const uint32_t bl_row0 = (uint32_t)((ng * 16 + li) * 256);
    const uint32_t bl_row1 = (uint32_t)((ng * 16 + 8 + li) * 256);
    const int blx0 = (ng * 16 + li) & 7, blx1 = (ng * 16 + 8 + li) & 7;

    const uint32_t W1L = sb, W2L = sb + 32768u;
    const uint32_t GB = sb + OFF_GRP + (uint32_t)grp * GRP_SIZE;
    const uint32_t HB = GB + 32768u;           // H hi; lo at +8192
    const int barid = grp + 1;

    // h epilogue addressing (mf=0; mf=1 adds 4096)
    const int hr0 = lane >> 2;
    uint32_t hadr[2][2];
#pragma unroll
    for (int ch = 0; ch < 2; ch++) {
        const int col = ng * 16 + ch * 8 + (lane & 3) * 2;
        const uint32_t u = (uint32_t)(col >> 3), w0 = (uint32_t)((col & 7) << 1);
        hadr[ch][0] = (uint32_t)(hr0 * 256) + ((u ^ (uint32_t)(hr0 & 7)) << 4) + w0;
        hadr[ch][1] = (uint32_t)((hr0 + 8) * 256) + ((u ^ (uint32_t)((hr0 + 8) & 7)) << 4) + w0;
    }

    // gather addressing: this warp gathers rows ng*4 .. ng*4+3 of its group's tile
    const uint32_t gwithin = (uint32_t)((lane & 1) << 3);
    const int gc = lane >> 1;
    const int grow = ng * 4;
    uint32_t gadr[4];
#pragma unroll
    for (int r = 0; r < 4; r++) {
        const int rr = grow + r;
        gadr[r] = (uint32_t)(rr * 256) + (uint32_t)((gc ^ (rr & 7)) << 4) + gwithin;
    }

    const int ntiles = (E + 31) >> 5;
    const int gi0 = blockIdx.x * 2 + grp;
    const int stride = gridDim.x * 2;
    if (gi0 >= ntiles) return;

#define GLDG(T, R, V) do {                                                \
        const int gr = ((T) << 5) + grow + (R);                           \
        const int o = (gr < E) ? g_idxp[gr] : 0;                          \
        V = *(const float4*)(x + o + (lane << 2));                        \
    } while (0)
#define GSTS(BASE, R, V) do {                                             \
        STS64((BASE) + gadr[R], pack4(V.x, V.y, V.z, V.w));               \
        STS64((BASE) + 8192u + gadr[R], pack4(rlo(V.x), rlo(V.y), rlo(V.z), rlo(V.w))); \
    } while (0)

    // ---- initial gather -> A0 ----
    {
        float4 v0, v1;
        GLDG(gi0, 0, v0); GLDG(gi0, 1, v1);
        GSTS(GB, 0, v0);  GSTS(GB, 1, v1);
        GLDG(gi0, 2, v0); GLDG(gi0, 3, v1);
        GSTS(GB, 2, v0);  GSTS(GB, 3, v1);
    }
    BAR_GRP(barid);

    const float* b1s = (const float*)(sm + OFF_B1);
    const float* b2s = (const float*)(sm + OFF_B2);

    for (int p = 0;; p++) {
        const int t = gi0 + p * stride;
        if (t >= ntiles) break;
        const int nt = t + stride;
        const uint32_t AR = GB + (uint32_t)(p & 1) * 16384u;          // A read
        const uint32_t AW = GB + (uint32_t)((p + 1) & 1) * 16384u;    // A write (gather)

        // ================= GEMM1: h = relu(A @ W1eff + b1) =================
        {
            float acc[2][2][4] = {};
#pragma unroll
            for (int ks = 0; ks < 8; ks++) {
                uint32_t Bl0[2], Bl1[2];
                ldsm_x2(Bl0, W1L + bl_row0 + (uint32_t)((((ks << 1) + bg) ^ blx0) << 4));
                ldsm_x2(Bl1, W1L + bl_row1 + (uint32_t)((((ks << 1) + bg) ^ blx1) << 4));
                const uint32_t c = (uint32_t)((((ks << 1) + akh) ^ arx) << 4);
#pragma unroll
                for (int mf = 0; mf < 2; mf++) {
                    uint32_t Ah[4], Al[4];
                    ldsm_x4(Ah, AR + (uint32_t)(mf * 4096) + arowoff + c);
                    ldsm_x4(Al, AR + 8192u + (uint32_t)(mf * 4096) + arowoff + c);
                    mma_bf16(acc[mf][0], Ah, B1h[0][ks]);
                    mma_bf16(acc[mf][1], Ah, B1h[1][ks]);
                    mma_bf16(acc[mf][0], Ah, Bl0);
                    mma_bf16(acc[mf][1], Ah, Bl1);
                    mma_bf16(acc[mf][0], Al, B1h[0][ks]);
                    mma_bf16(acc[mf][1], Al, B1h[1][ks]);
                }
            }
            // epilogue -> H hi/lo
#pragma unroll
            for (int mf = 0; mf < 2; mf++) {
                const uint32_t mo = (uint32_t)(mf * 4096);
#pragma unroll
                for (int ch = 0; ch < 2; ch++) {
                    const int cidx = ng * 16 + ch * 8 + (lane & 3) * 2;
                    const float ba = b1s[cidx], bb = b1s[cidx + 1];
                    const float f0 = fmaxf(acc[mf][ch][0] + ba, 0.f);
                    const float f1 = fmaxf(acc[mf][ch][1] + bb, 0.f);
                    const float f2 = fmaxf(acc[mf][ch][2] + ba, 0.f);
                    const float f3 = fmaxf(acc[mf][ch][3] + bb, 0.f);
                    STS32(HB + mo + hadr[ch][0], pack2(f0, f1));
                    STS32(HB + 8192u + mo + hadr[ch][0], pack2(rlo(f0), rlo(f1)));
                    STS32(HB + mo + hadr[ch][1], pack2(f2, f3));
                    STS32(HB + 8192u + mo + hadr[ch][1], pack2(rlo(f2), rlo(f3)));
                }
            }
        }
        BAR_GRP(barid);   // H ready; A[cur] consumed

        // ================= GEMM2 (+ staggered gather of next tile) =================
        {
            const bool hasN = (nt < ntiles);
            float4 v0, v1;
            if (hasN) { GLDG(nt, 0, v0); GLDG(nt, 1, v1); }

            float acc[2][2][4] = {};
#pragma unroll
            for (int ks = 0; ks < 8; ks++) {
                if (ks == 4 && hasN) {     // mid-loop: store rows 0,1; fetch rows 2,3
                    GSTS(AW, 0, v0); GSTS(AW, 1, v1);
                    GLDG(nt, 2, v0); GLDG(nt, 3, v1);
                }
                uint32_t Bl0[2], Bl1[2];
                ldsm_x2(Bl0, W2L + bl_row0 + (uint32_t)((((ks << 1) + bg) ^ blx0) << 4));
                ldsm_x2(Bl1, W2L + bl_row1 + (uint32_t)((((ks << 1) + bg) ^ blx1) << 4));
                const uint32_t c = (uint32_t)((((ks << 1) + akh) ^ arx) << 4);
#pragma unroll
                for (int mf = 0; mf < 2; mf++) {
                    uint32_t Ah[4], Al[4];
                    ldsm_x4(Ah, HB + (uint32_t)(mf * 4096) + arowoff + c);
                    ldsm_x4(Al, HB + 8192u + (uint32_t)(mf * 4096) + arowoff + c);
                    mma_bf16(acc[mf][0], Ah, B2h[0][ks]);
                    mma_bf16(acc[mf][1], Ah, B2h[1][ks]);
                    mma_bf16(acc[mf][0], Ah, Bl0);
                    mma_bf16(acc[mf][1], Ah, Bl1);
                    mma_bf16(acc[mf][0], Al, B2h[0][ks]);
                    mma_bf16(acc[mf][1], Al, B2h[1][ks]);
                }
            }
            if (hasN) { GSTS(AW, 2, v0); GSTS(AW, 3, v1); }

            // epilogue -> global
#pragma unroll
            for (int mf = 0; mf < 2; mf++) {
                const int rg0 = (t << 5) + mf * 16 + (lane >> 2);
                const int rg1 = rg0 + 8;
#pragma unroll
                for (int ch = 0; ch < 2; ch++) {
                    const int col = ng * 16 + ch * 8 + (lane & 3) * 2;
                    const float ba = b2s[col], bb = b2s[col + 1];
                    if (rg0 < E)
                        *(float2*)(out + (size_t)rg0 * 128 + col) =
                            make_float2(acc[mf][ch][0] + ba, acc[mf][ch][1] + bb);
                    if (rg1 < E)
                        *(float2*)(out + (size_t)rg1 * 128 + col) =
                            make_float2(acc[mf][ch][2] + ba, acc[mf][ch][3] + bb);
                }
            }
        }
        BAR_GRP(barid);   // H consumed; next A complete
    }
#undef GLDG
#undef GSTS
}

// ======================= launch =======================
extern "C" void kernel_launch(void* const* d_in, const int* in_sizes, int n_in,
                              void* d_out, int out_size) {
    const float* x  = (const float*)d_in[0];
    const void*  nb = d_in[1];
    const float* W1 = (const float*)d_in[2];
    const float* b1 = (const float*)d_in[3];
    const float* W2 = (const float*)d_in[4];
    const float* b2 = (const float*)d_in[5];
    float* out = (float*)d_out;
    const int E = in_sizes[1];

    int pg = (E + 255) / 256;
    if (pg < 128) pg = 128;
    prep_all<<<pg, 256>>>(W1, W2, nb, E);

    int dev = 0;
    cudaGetDevice(&dev);
    int sms = 148;
    cudaDeviceGetAttribute(&sms, cudaDevAttrMultiProcessorCount, dev);
    const int ntiles = (E + 31) >> 5;
    int grid = sms;
    const int maxg = (ntiles + 1) / 2;
    if (grid > maxg) grid = maxg;

    cudaFuncSetAttribute(gs_kernel, cudaFuncAttributeMaxDynamicSharedMemorySize, SMEM_TOTAL);
    gs_kernel<<<grid, 512, SMEM_TOTAL>>>(x, b1, b2, out, E);
}

// round 8
// speedup vs baseline: 2.4113x; 1.8686x over previous
#include <cuda_runtime.h>
#include <cuda_bf16.h>
#include <cstdint>

#define DINL __device__ __forceinline__

DINL uint32_t smem_u32(const void* p) {
    uint32_t a;
    asm("{ .reg .u64 t; cvta.to.shared.u64 t, %1; cvt.u32.u64 %0, t; }" : "=r"(a) : "l"(p));
    return a;
}
DINL void ldsm_x4(uint32_t r[4], uint32_t addr) {
    asm volatile("ldmatrix.sync.aligned.m8n8.x4.shared.b16 {%0,%1,%2,%3}, [%4];"
        : "=r"(r[0]), "=r"(r[1]), "=r"(r[2]), "=r"(r[3]) : "r"(addr));
}
DINL void ldsm_x2(uint32_t r[2], uint32_t addr) {
    asm volatile("ldmatrix.sync.aligned.m8n8.x2.shared.b16 {%0,%1}, [%2];"
        : "=r"(r[0]), "=r"(r[1]) : "r"(addr));
}
DINL void mma_bf16(float c[4], const uint32_t a[4], const uint32_t b[2]) {
    asm volatile("mma.sync.aligned.m16n8k16.row.col.f32.bf16.bf16.f32 "
        "{%0,%1,%2,%3}, {%4,%5,%6,%7}, {%8,%9}, {%0,%1,%2,%3};"
        : "+f"(c[0]), "+f"(c[1]), "+f"(c[2]), "+f"(c[3])
        : "r"(a[0]), "r"(a[1]), "r"(a[2]), "r"(a[3]), "r"(b[0]), "r"(b[1]));
}
#define STS64(a, v)  asm volatile("st.shared.b64 [%0], %1;" :: "r"(a), "l"(v) : "memory")
#define STS128(a, v) asm volatile("st.shared.v4.b32 [%0], {%1,%2,%3,%4};" \
    :: "r"(a), "r"((v).x), "r"((v).y), "r"((v).z), "r"((v).w) : "memory")
#define BAR_GRP(id) asm volatile("bar.sync %0, 128;" :: "r"(id) : "memory")

DINL uint32_t pack2(float a, float b) {
    return ((uint32_t)__bfloat16_as_ushort(__float2bfloat16(b)) << 16)
         |  (uint32_t)__bfloat16_as_ushort(__float2bfloat16(a));
}
DINL uint64_t pack4(float a, float b, float c, float d) {
    return ((uint64_t)pack2(c, d) << 32) | (uint64_t)pack2(a, b);
}
DINL float rlo(float f) { return f - __bfloat162float(__float2bfloat16(f)); }

__device__ __align__(16) uint32_t g_w1h[8192];
__device__ __align__(16) unsigned char g_w1l[32768];
__device__ __align__(16) unsigned char g_w2h[32768];
__device__ __align__(16) unsigned char g_w2l[32768];
__device__ __align__(16) float g_b2[128];
static constexpr int IDX_CAP = 1 << 20;
__device__ int g_idxp[IDX_CAP];
static constexpr int H_CAP = 1 << 23;
__device__ __align__(16) __nv_bfloat16 g_Hhi[H_CAP];
__device__ __align__(16) __nv_bfloat16 g_Hlo[H_CAP];

__global__ void prep_all(const float* __restrict__ W1, const float* __restrict__ W2,
                         const float* __restrict__ b2, const void* __restrict__ nbr_raw, int E) {
    __shared__ int s_is64;
    if (threadIdx.x == 0) {
        const unsigned* w = (const unsigned*)nbr_raw;
        int is64 = 1;
        for (int i = 0; i < 64; i++)
            if (w[2 * i + 1] != 0u) { is64 = 0; break; }
        s_is64 = is64;
    }
    __syncthreads();
    const int i = blockIdx.x * 256 + threadIdx.x;
    if (i < E && i < IDX_CAP) {
        long long v = s_is64 ? ((const long long*)nbr_raw)[i]
                             : (long long)((const int*)nbr_raw)[i];
        g_idxp[i] = ((int)v) << 7;
    }
    if (blockIdx.x == 0 && threadIdx.x < 128) g_b2[threadIdx.x] = b2[threadIdx.x];
    if (blockIdx.x < 128 && threadIdx.x < 128) {
        const int n = blockIdx.x, k = threadIdx.x;
        float w1e = W1[k * 128 + n] + W1[(k + 128) * 128 + n];
        float w2v = W2[k * 128 + n];
        __nv_bfloat16 h1 = __float2bfloat16(w1e);
        __nv_bfloat16 l1 = __float2bfloat16(w1e - __bfloat162float(h1));
        __nv_bfloat16 h2 = __float2bfloat16(w2v);
        __nv_bfloat16 l2 = __float2bfloat16(w2v - __bfloat162float(h2));
        ((__nv_bfloat16*)g_w1h)[n * 128 + k] = h1;
        uint32_t ta = (uint32_t)(n * 256 + (((k >> 3) ^ (n & 7)) << 4) + ((k & 7) << 1));
        *(__nv_bfloat16*)(g_w1l + ta) = l1;
        *(__nv_bfloat16*)(g_w2h + ta) = h2;
        *(__nv_bfloat16*)(g_w2l + ta) = l2;
    }
}

// ============ phase 1: H = relu(x @ W1eff + b1) per node ============
static constexpr int P1_W1L = 16384;
static constexpr int P1_B1  = 49152;
static constexpr int P1_SMEM = 49664;

__global__ void __launch_bounds__(256, 1)
prep_h(const float* __restrict__ x, const float* __restrict__ b1, int nodes) {
    extern __shared__ unsigned char sm[];
    const uint32_t sb = smem_u32(sm);
    const int tid = threadIdx.x, wid = tid >> 5, lane = tid & 31;

    {
        const uint4* s = (const uint4*)g_w1l;
        uint4* d = (uint4*)(sm + P1_W1L);
#pragma unroll
        for (int i = tid; i < 2048; i += 256) d[i] = s[i];
    }
    if (tid < 128) ((float*)(sm + P1_B1))[tid] = b1[tid];

    uint32_t B1h[2][8][2];
    {
        const int lc = lane & 3;
#pragma unroll
        for (int ch = 0; ch < 2; ch++) {
            const int nb = (wid * 16 + ch * 8 + (lane >> 2)) * 64;
#pragma unroll
            for (int ks = 0; ks < 8; ks++)
#pragma unroll
                for (int j = 0; j < 2; j++)
                    B1h[ch][ks][j] = g_w1h[nb + ks * 8 + j * 4 + lc];
        }
    }

    const int rb = blockIdx.x * 32;
    {
        const int r = tid >> 3, part = tid & 7;
        const bool ok = (rb + r) < nodes;
        const float4* xr = (const float4*)(x + (size_t)(rb + r) * 128 + part * 16);
#pragma unroll
        for (int i = 0; i < 4; i++) {
            float4 v = ok ? xr[i] : make_float4(0.f, 0.f, 0.f, 0.f);
            const int c0 = part * 16 + i * 4;
            const uint32_t a = (uint32_t)(r * 256 + (((c0 >> 3) ^ (r & 7)) << 4) + ((c0 & 7) << 1));
            STS64(sb + a, pack4(v.x, v.y, v.z, v.w));
            STS64(sb + 8192u + a, pack4(rlo(v.x), rlo(v.y), rlo(v.z), rlo(v.w)));
        }
    }
    __syncthreads();

    const int li = lane & 7, lg = lane >> 3;
    const int arow = ((lg & 1) << 3) + li;
    const int akh = lg >> 1;
    const uint32_t arowoff = (uint32_t)(arow * 256);
    const int arx = arow & 7;
    const int bg = lg & 1;
    const uint32_t bl_row0 = (uint32_t)((wid * 16 + li) * 256);
    const uint32_t bl_row1 = (uint32_t)((wid * 16 + 8 + li) * 256);
    const int blx0 = (wid * 16 + li) & 7, blx1 = (wid * 16 + 8 + li) & 7;
    const uint32_t W1Ls = sb + P1_W1L;

    float acc[2][2][4] = {};
#pragma unroll
    for (int ks = 0; ks < 8; ks++) {
        uint32_t Bl0[2], Bl1[2];
        ldsm_x2(Bl0, W1Ls + bl_row0 + (uint32_t)((((ks << 1) + bg) ^ blx0) << 4));
        ldsm_x2(Bl1, W1Ls + bl_row1 + (uint32_t)((((ks << 1) + bg) ^ blx1) << 4));
        const uint32_t c = (uint32_t)((((ks << 1) + akh) ^ arx) << 4);
#pragma unroll
        for (int mf = 0; mf < 2; mf++) {
            uint32_t Ah[4], Al[4];
            ldsm_x4(Ah, sb + (uint32_t)(mf * 4096) + arowoff + c);
            ldsm_x4(Al, sb + 8192u + (uint32_t)(mf * 4096) + arowoff + c);
            mma_bf16(acc[mf][0], Ah, B1h[0][ks]);
            mma_bf16(acc[mf][1], Ah, B1h[1][ks]);
            mma_bf16(acc[mf][0], Ah, Bl0);
            mma_bf16(acc[mf][1], Ah, Bl1);
            mma_bf16(acc[mf][0], Al, B1h[0][ks]);
            mma_bf16(acc[mf][1], Al, B1h[1][ks]);
        }
    }

    const float* b1s = (const float*)(sm + P1_B1);
#pragma unroll
    for (int mf = 0; mf < 2; mf++) {
        const int gr0 = rb + mf * 16 + (lane >> 2), gr1 = gr0 + 8;
#pragma unroll
        for (int ch = 0; ch < 2; ch++) {
            const int col = wid * 16 + ch * 8 + (lane & 3) * 2;
            const float ba = b1s[col], bb = b1s[col + 1];
            const float f0 = fmaxf(acc[mf][ch][0] + ba, 0.f);
            const float f1 = fmaxf(acc[mf][ch][1] + bb, 0.f);
            const float f2 = fmaxf(acc[mf][ch][2] + ba, 0.f);
            const float f3 = fmaxf(acc[mf][ch][3] + bb, 0.f);
            if (gr0 < nodes) {
                *(uint32_t*)(g_Hhi + (size_t)gr0 * 128 + col) = pack2(f0, f1);
                *(uint32_t*)(g_Hlo + (size_t)gr0 * 128 + col) = pack2(rlo(f0), rlo(f1));
            }
            if (gr1 < nodes) {
                *(uint32_t*)(g_Hhi + (size_t)gr1 * 128 + col) = pack2(f2, f3);
                *(uint32_t*)(g_Hlo + (size_t)gr1 * 128 + col) = pack2(rlo(f2), rlo(f3));
            }
        }
    }
}

// ============ phase 2: y = H[idx] @ W2 + b2 ============
static constexpr int P2_GRP = 65536;
static constexpr int P2_B2  = 196608;
static constexpr int P2_SMEM = 197120;

__global__ void __launch_bounds__(512, 1)
gs2_kernel(float* __restrict__ out, int E) {
    extern __shared__ unsigned char sm[];
    const uint32_t sb = smem_u32(sm);
    const int tid = threadIdx.x, wid = tid >> 5, lane = tid & 31;
    const int grp = wid >> 2, nw = wid & 3;

    {
        const uint4* sh = (const uint4*)g_w2h;
        const uint4* sl = (const uint4*)g_w2l;
        uint4* dh = (uint4*)sm;
        uint4* dl = (uint4*)(sm + 32768);
#pragma unroll
        for (int i = tid; i < 2048; i += 512) { dh[i] = sh[i]; dl[i] = sl[i]; }
    }
    if (tid < 128) ((float*)(sm + P2_B2))[tid] = g_b2[tid];
    __syncthreads();

    const uint32_t W2H = sb, W2L = sb + 32768u;
    const uint32_t GB = sb + P2_GRP + (uint32_t)grp * 32768u;
    const int barid = grp + 1;

    const int li = lane & 7, lg = lane >> 3;
    const int arow = ((lg & 1) << 3) + li;
    const int akh = lg >> 1;
    const uint32_t arowoff = (uint32_t)(arow * 256);
    const int arx = arow & 7;

    const int mi = lg;
    const int bkj = mi & 1;
    const int brow_a = nw * 32 + ((mi >> 1) << 3) + li;
    const int brow_b = brow_a + 16;
    const uint32_t boff_a = (uint32_t)(brow_a * 256);
    const uint32_t boff_b = (uint32_t)(brow_b * 256);
    const int brx_a = brow_a & 7, brx_b = brow_b & 7;

    const int grow0 = nw * 8 + (lane >> 4);
    const int gchunk = lane & 15;
    const int goff16 = gchunk * 16;
    uint32_t gadr[4];
#pragma unroll
    for (int q = 0; q < 4; q++) {
        const int r = grow0 + q * 2;
        gadr[q] = (uint32_t)(r * 256 + ((gchunk ^ (r & 7)) << 4));
    }
    const char* hbhi = (const char*)g_Hhi;
    const char* hblo = (const char*)g_Hlo;

    const int ntiles = (E + 31) >> 5;
    const int g_abs = blockIdx.x * 4 + grp;
    const int stride = gridDim.x * 4;
    if (g_abs >= ntiles) return;

#define GLDG2(T, Q, VH, VL) do {                                          \
        const int gr = ((T) << 5) + grow0 + (Q) * 2;                      \
        const int off = ((gr < E) ? g_idxp[gr] : 0) * 2 + goff16;         \
        VH = *(const uint4*)(hbhi + off);                                 \
        VL = *(const uint4*)(hblo + off);                                 \
    } while (0)
#define GSTS2(BASE, Q, VH, VL) do {                                       \
        STS128((BASE) + gadr[Q], VH);                                     \
        STS128((BASE) + 8192u + gadr[Q], VL);                             \
    } while (0)

    {
        uint4 h0, l0, h1, l1;
        GLDG2(g_abs, 0, h0, l0); GLDG2(g_abs, 1, h1, l1);
        GSTS2(GB, 0, h0, l0);    GSTS2(GB, 1, h1, l1);
        GLDG2(g_abs, 2, h0, l0); GLDG2(g_abs, 3, h1, l1);
        GSTS2(GB, 2, h0, l0);    GSTS2(GB, 3, h1, l1);
    }
    BAR_GRP(barid);

    const float* b2s = (const float*)(sm + P2_B2);

    for (int p = 0;; p++) {
        const int t = g_abs + p * stride;
        if (t >= ntiles) break;
        const int nt = t + stride;
        const bool hasN = (nt < ntiles);
        const uint32_t AR = GB + (uint32_t)(p & 1) * 16384u;
        const uint32_t AW = GB + (uint32_t)((p + 1) & 1) * 16384u;

        uint4 vh0, vl0, vh1, vl1;
        if (hasN) { GLDG2(nt, 0, vh0, vl0); GLDG2(nt, 1, vh1, vl1); }

        float acc[2][4][4] = {};
#pragma unroll
        for (int ks = 0; ks < 8; ks++) {
            if (ks == 3 && hasN) {
                GSTS2(AW, 0, vh0, vl0); GSTS2(AW, 1, vh1, vl1);
                GLDG2(nt, 2, vh0, vl0); GLDG2(nt, 3, vh1, vl1);
            }
            const uint32_t cka = (uint32_t)((((ks << 1) + bkj) ^ brx_a) << 4);
            const uint32_t ckb = (uint32_t)((((ks << 1) + bkj) ^ brx_b) << 4);
            uint32_t Bh01[4], Bh23[4], Bl01[4], Bl23[4];
            ldsm_x4(Bh01, W2H + boff_a + cka);
            ldsm_x4(Bh23, W2H + boff_b + ckb);
            ldsm_x4(Bl01, W2L + boff_a + cka);
            ldsm_x4(Bl23, W2L + boff_b + ckb);
            const uint32_t c = (uint32_t)((((ks << 1) + akh) ^ arx) << 4);
#pragma unroll
            for (int mf = 0; mf < 2; mf++) {
                uint32_t Ah[4], Al[4];
                ldsm_x4(Ah, AR + (uint32_t)(mf * 4096) + arowoff + c);
                ldsm_x4(Al, AR + 8192u + (uint32_t)(mf * 4096) + arowoff + c);
                mma_bf16(acc[mf][0], Ah, Bh01 + 0);
                mma_bf16(acc[mf][1], Ah, Bh01 + 2);
                mma_bf16(acc[mf][2], Ah, Bh23 + 0);
                mma_bf16(acc[mf][3], Ah, Bh23 + 2);
                mma_bf16(acc[mf][0], Ah, Bl01 + 0);
                mma_bf16(acc[mf][1], Ah, Bl01 + 2);
                mma_bf16(acc[mf][2], Ah, Bl23 + 0);
                mma_bf16(acc[mf][3], Ah, Bl23 + 2);
                mma_bf16(acc[mf][0], Al, Bh01 + 0);
                mma_bf16(acc[mf][1], Al, Bh01 + 2);
                mma_bf16(acc[mf][2], Al, Bh23 + 0);
                mma_bf16(acc[mf][3], Al, Bh23 + 2);
            }
        }
        if (hasN) { GSTS2(AW, 2, vh0, vl0); GSTS2(AW, 3, vh1, vl1); }

#pragma unroll
        for (int mf = 0; mf < 2; mf++) {
            const int rg0 = (t << 5) + mf * 16 + (lane >> 2), rg1 = rg0 + 8;
#pragma unroll
            for (int cc = 0; cc < 4; cc++) {
                const int col = nw * 32 + cc * 8 + (lane & 3) * 2;
                const float ba = b2s[col], bb = b2s[col + 1];
                if (rg0 < E)
                    *(float2*)(out + (size_t)rg0 * 128 + col) =
                        make_float2(acc[mf][cc][0] + ba, acc[mf][cc][1] + bb);
                if (rg1 < E)
                    *(float2*)(out + (size_t)rg1 * 128 + col) =
                        make_float2(acc[mf][cc][2] + ba, acc[mf][cc][3] + bb);
            }
        }
        BAR_GRP(barid);
    }
#undef GLDG2
#undef GSTS2
}

// ======================= launch =======================
extern "C" void kernel_launch(void* const* d_in, const int* in_sizes, int n_in,
                              void* d_out, int out_size) {
    const float* x  = (const float*)d_in[0];
    const void*  nb = d_in[1];
    const float* W1 = (const float*)d_in[2];
    const float* b1 = (const float*)d_in[3];
    const float* W2 = (const float*)d_in[4];
    const float* b2 = (const float*)d_in[5];
    float* out = (float*)d_out;
    const int E = in_sizes[1];
    const int nodes = in_sizes[0] / 128;

    int pg = (E + 255) / 256;
    if (pg < 128) pg = 128;
    prep_all<<<pg, 256>>>(W1, W2, b2, nb, E);

    cudaFuncSetAttribute(prep_h, cudaFuncAttributeMaxDynamicSharedMemorySize, P1_SMEM);
    prep_h<<<(nodes + 31) / 32, 256, P1_SMEM>>>(x, b1, nodes);

    int dev = 0;
    cudaGetDevice(&dev);
    int sms = 148;
    cudaDeviceGetAttribute(&sms, cudaDevAttrMultiProcessorCount, dev);
    const int ntiles = (E + 31) >> 5;
    int grid = sms;
    const int maxg = (ntiles + 3) / 4;
    if (grid > maxg) grid = maxg;

    cudaFuncSetAttribute(gs2_kernel, cudaFuncAttributeMaxDynamicSharedMemorySize, P2_SMEM);
    gs2_kernel<<<grid, 512, P2_SMEM>>>(out, E);
}